// round 6
// baseline (speedup 1.0000x reference)
#include <cuda_runtime.h>
#include <cuda_fp16.h>
#include <math.h>
#include <stdint.h>

// ---------------- problem constants ----------------
#define BB 2
#define TT 2048
#define DD 1024
#define HH 16
#define HD 64
#define NL 6
#define DF 4096
#define NTOK (BB*TT)          // 4096 rows
#define QKVLD 5120            // fused QKVZR row stride
#define EPSLN 1e-5f

// ---------------- device scratch (no allocs allowed) ----------------
__device__ float  g_x   [NTOK*DD];
__device__ __half g_xn  [NTOK*DD];
__device__ __half g_qkvzr[(size_t)NTOK*QKVLD];
__device__ __half g_y   [NTOK*DD];
__device__ float  g_zs  [NTOK*DD];
__device__ __half g_h1  [(size_t)NTOK*DF];

// transposed fp16 weights, K-major [N][K]
__device__ __half g_wtqkvzr[(size_t)NL*QKVLD*DD];
__device__ __half g_wto    [(size_t)NL*DD*DD];
__device__ __half g_wt1    [(size_t)NL*DF*DD];
__device__ __half g_wt2    [(size_t)NL*DD*DF];
__device__ float  g_bcat   [NL*QKVLD];

// ---------------- helpers ----------------
__device__ __forceinline__ float exp2a(float x) {
    float y;
    asm("ex2.approx.f32 %0, %1;" : "=f"(y) : "f"(x));
    return y;
}

__device__ __forceinline__ void mma_f16(float* d, const uint32_t* a, const uint32_t* b) {
    asm volatile(
        "mma.sync.aligned.m16n8k16.row.col.f32.f16.f16.f32 "
        "{%0,%1,%2,%3}, {%4,%5,%6,%7}, {%8,%9}, {%0,%1,%2,%3};"
        : "+f"(d[0]), "+f"(d[1]), "+f"(d[2]), "+f"(d[3])
        : "r"(a[0]), "r"(a[1]), "r"(a[2]), "r"(a[3]),
          "r"(b[0]), "r"(b[1]));
}

__device__ __forceinline__ float sigmoidf_(float x) { return 1.0f / (1.0f + expf(-x)); }

__device__ __forceinline__ uint32_t smem_u32(const void* p) {
    uint32_t a;
    asm("{ .reg .u64 t; cvta.to.shared.u64 t, %1; cvt.u32.u64 %0, t; }" : "=r"(a) : "l"(p));
    return a;
}

__device__ __forceinline__ void cp16(uint32_t dst, const void* src) {
    asm volatile("cp.async.cg.shared.global [%0], [%1], 16;" :: "r"(dst), "l"(src) : "memory");
}
#define CP_COMMIT() asm volatile("cp.async.commit_group;" ::: "memory")
#define CP_WAIT(n)  asm volatile("cp.async.wait_group %0;" :: "n"(n) : "memory")

// ---------------- small elementwise kernels ----------------
__global__ void copy_kernel(float* __restrict__ dst, const float* __restrict__ src, int n) {
    int i = blockIdx.x * blockDim.x + threadIdx.x;
    if (i < n) dst[i] = src[i];
}

// ---------------- layernorm (fp16 out / fp32 out) ----------------
template <typename OutT>
__global__ __launch_bounds__(256) void layernorm_kernel(
        const float* __restrict__ x, const float* __restrict__ w,
        const float* __restrict__ b, OutT* __restrict__ out) {
    int row = blockIdx.x;
    const float* xr = x + (size_t)row * DD;
    OutT* orow = out + (size_t)row * DD;
    int tid = threadIdx.x;
    __shared__ float s1[256], s2[256];
    float sum = 0.f, ss = 0.f;
    #pragma unroll
    for (int j = tid; j < DD; j += 256) { float v = xr[j]; sum += v; ss += v * v; }
    s1[tid] = sum; s2[tid] = ss;
    __syncthreads();
    for (int s = 128; s > 0; s >>= 1) {
        if (tid < s) { s1[tid] += s1[tid + s]; s2[tid] += s2[tid + s]; }
        __syncthreads();
    }
    float mu = s1[0] * (1.0f / DD);
    float var = s2[0] * (1.0f / DD) - mu * mu;
    float rs = rsqrtf(var + EPSLN);
    for (int j = tid; j < DD; j += 256)
        orow[j] = (OutT)((xr[j] - mu) * rs * w[j] + b[j]);
}

// ---------------- batched weight transpose to fp16 (z = layer) ----------------
__global__ __launch_bounds__(256) void transpose_h_kernel(
        const float* __restrict__ src, __half* __restrict__ dst, int K, int N,
        size_t srcLS, size_t dstLS) {
    __shared__ float tile[32][33];
    const float* s = src + blockIdx.z * srcLS;
    __half* d = dst + blockIdx.z * dstLS;
    int k0 = blockIdx.y * 32, n0 = blockIdx.x * 32;
    int tx = threadIdx.x & 31, ty = threadIdx.x >> 5;
    #pragma unroll
    for (int i = 0; i < 4; i++)
        tile[ty + i * 8][tx] = s[(size_t)(k0 + ty + i * 8) * N + n0 + tx];
    __syncthreads();
    #pragma unroll
    for (int i = 0; i < 4; i++)
        d[(size_t)(n0 + ty + i * 8) * K + k0 + tx] = __float2half(tile[tx][ty + i * 8]);
}

__global__ void biaspack_kernel(const float* __restrict__ bq, const float* __restrict__ bk,
                                const float* __restrict__ bv, const float* __restrict__ bz,
                                const float* __restrict__ br, float* __restrict__ out) {
    int i = blockIdx.x * blockDim.x + threadIdx.x;
    if (i >= NL * QKVLD) return;
    int l = i / QKVLD, j = i % QKVLD;
    int m = j >> 10, c = j & 1023;
    const float* src = (m == 0) ? bq : (m == 1) ? bk : (m == 2) ? bv : (m == 3) ? bz : br;
    out[i] = src[l * 1024 + c];
}

// ---------------- fp16 tensor-core GEMM, 3-stage cp.async ----------------
// C[M,N] = A[M,K](fp16) @ WT[N,K]^T(fp16) + bias. BM=BN=128, BK=64.
// epi: 0=bias->out, 1=bias+GELU->out, 2=gate1(x,zs), 3=gate2(x)
#define GBM 128
#define GBN 128
#define GBK 64
#define GP 72   // smem pitch in halves
#define GTILE (GBM*GP)
#define NSTAGE 3
#define GEMM_SMEM (2*NSTAGE*GTILE*2)

struct EpiArgs {
    float* xbuf;            // gate modes: residual x (fp32, ld=DD)
    float* zsbuf;           // gate1: z out; gate2: z in
    const __half* qz;       // gate1: fused qkvzr (z/r logits)
    const float* srcp;      // gate2: original sequences
};

__global__ __launch_bounds__(256) void gemm_f16_kernel(
        const __half* __restrict__ A, const __half* __restrict__ WT,
        const float* __restrict__ bias, void* __restrict__ Cout,
        int K, int ldC, int epi, int outHalf, EpiArgs ea) {
    extern __shared__ char dynsm[];
    __half* As = (__half*)dynsm;
    __half* Bs = As + NSTAGE * GTILE;

    const int tid  = threadIdx.x;
    const int warp = tid >> 5;
    const int lane = tid & 31;
    const int g    = lane >> 2;
    const int tg   = lane & 3;
    const int row0 = blockIdx.y * GBM;
    const int col0 = blockIdx.x * GBN;
    const int wm   = (warp >> 2) * 64;
    const int wn   = (warp & 3) * 32;

    const int fr = tid >> 3;
    const int fc = (tid & 7) * 8;

    float acc[4][4][4];
    #pragma unroll
    for (int i = 0; i < 4; i++)
        #pragma unroll
        for (int j = 0; j < 4; j++)
            #pragma unroll
            for (int c = 0; c < 4; c++) acc[i][j][c] = 0.f;

    const __half* Ag = A  + (size_t)row0 * K;
    const __half* Bg = WT + (size_t)col0 * K;
    const uint32_t as_base = smem_u32(As);
    const uint32_t bs_base = smem_u32(Bs);

    auto issue = [&](int it, int buf) {
        const int k0 = it * GBK;
        uint32_t ad = as_base + (buf * GTILE) * 2;
        uint32_t bd = bs_base + (buf * GTILE) * 2;
        #pragma unroll
        for (int i = 0; i < 4; i++) {
            int r = fr + i * 32;
            cp16(ad + (r * GP + fc) * 2, Ag + (size_t)r * K + k0 + fc);
            cp16(bd + (r * GP + fc) * 2, Bg + (size_t)r * K + k0 + fc);
        }
    };

    const int nit = K / GBK;
    issue(0, 0); CP_COMMIT();
    if (nit > 1) { issue(1, 1); CP_COMMIT(); }

    for (int it = 0; it < nit; it++) {
        const int buf = it % NSTAGE;
        if (it + 1 < nit) CP_WAIT(1); else CP_WAIT(0);
        __syncthreads();
        if (it + 2 < nit) { issue(it + 2, (it + 2) % NSTAGE); CP_COMMIT(); }

        const __half* Ab = As + buf * GTILE;
        const __half* Bb = Bs + buf * GTILE;
        #pragma unroll
        for (int ks = 0; ks < 4; ks++) {
            const int kc = ks * 16;
            uint32_t af[4][4], bf[4][2];
            #pragma unroll
            for (int fm = 0; fm < 4; fm++) {
                const __half* p = Ab + (wm + fm * 16 + g) * GP + kc + 2 * tg;
                af[fm][0] = *(const uint32_t*)p;
                af[fm][1] = *(const uint32_t*)(p + 8 * GP);
                af[fm][2] = *(const uint32_t*)(p + 8);
                af[fm][3] = *(const uint32_t*)(p + 8 * GP + 8);
            }
            #pragma unroll
            for (int fn = 0; fn < 4; fn++) {
                const __half* q = Bb + (wn + fn * 8 + g) * GP + kc + 2 * tg;
                bf[fn][0] = *(const uint32_t*)q;
                bf[fn][1] = *(const uint32_t*)(q + 8);
            }
            #pragma unroll
            for (int fm = 0; fm < 4; fm++)
                #pragma unroll
                for (int fn = 0; fn < 4; fn++)
                    mma_f16(acc[fm][fn], af[fm], bf[fn]);
        }
    }

    // ---------------- epilogue ----------------
    #pragma unroll
    for (int fm = 0; fm < 4; fm++) {
        int r1 = row0 + wm + fm * 16 + g;
        #pragma unroll
        for (int fn = 0; fn < 4; fn++) {
            int cl = wn + fn * 8 + tg * 2;
            int cg0 = col0 + cl;
            float bz0 = bias[cg0];
            float bz1 = bias[cg0 + 1];
            float v00 = acc[fm][fn][0] + bz0;
            float v01 = acc[fm][fn][1] + bz1;
            float v10 = acc[fm][fn][2] + bz0;
            float v11 = acc[fm][fn][3] + bz1;

            if (epi == 0) {
                if (outHalf) {
                    __half* ch = (__half*)Cout;
                    *(__half2*)(ch + (size_t)r1 * ldC + cg0) = __floats2half2_rn(v00, v01);
                    *(__half2*)(ch + (size_t)(r1 + 8) * ldC + cg0) = __floats2half2_rn(v10, v11);
                } else {
                    float* cf = (float*)Cout;
                    float2 o0 = {v00, v01};
                    float2 o1 = {v10, v11};
                    *(float2*)(cf + (size_t)r1 * ldC + cg0) = o0;
                    *(float2*)(cf + (size_t)(r1 + 8) * ldC + cg0) = o1;
                }
            } else if (epi == 1) {
                v00 = 0.5f * v00 * (1.0f + erff(v00 * 0.70710678118654752440f));
                v01 = 0.5f * v01 * (1.0f + erff(v01 * 0.70710678118654752440f));
                v10 = 0.5f * v10 * (1.0f + erff(v10 * 0.70710678118654752440f));
                v11 = 0.5f * v11 * (1.0f + erff(v11 * 0.70710678118654752440f));
                __half* ch = (__half*)Cout;
                *(__half2*)(ch + (size_t)r1 * ldC + cg0) = __floats2half2_rn(v00, v01);
                *(__half2*)(ch + (size_t)(r1 + 8) * ldC + cg0) = __floats2half2_rn(v10, v11);
            } else if (epi == 2) {
                // gate1: x = (1-z)x + z*tanh(r*v); zs = z
                #pragma unroll
                for (int h = 0; h < 2; h++) {
                    int rr = r1 + h * 8;
                    float va = h ? v10 : v00;
                    float vb = h ? v11 : v01;
                    size_t qb_ = (size_t)rr * QKVLD + cg0;
                    float z0 = sigmoidf_(__half2float(ea.qz[qb_ + 3072]));
                    float z1 = sigmoidf_(__half2float(ea.qz[qb_ + 3073]));
                    float rg0 = sigmoidf_(__half2float(ea.qz[qb_ + 4096]));
                    float rg1 = sigmoidf_(__half2float(ea.qz[qb_ + 4097]));
                    size_t xi = (size_t)rr * DD + cg0;
                    float2 xv = *(float2*)(ea.xbuf + xi);
                    float h0 = tanhf(rg0 * va);
                    float h1v = tanhf(rg1 * vb);
                    float2 xo = {(1.0f - z0) * xv.x + z0 * h0,
                                 (1.0f - z1) * xv.y + z1 * h1v};
                    *(float2*)(ea.xbuf + xi) = xo;
                    float2 zo = {z0, z1};
                    *(float2*)(ea.zsbuf + xi) = zo;
                }
            } else {
                // gate2: x = (1-z)x + z*v + src
                #pragma unroll
                for (int h = 0; h < 2; h++) {
                    int rr = r1 + h * 8;
                    float va = h ? v10 : v00;
                    float vb = h ? v11 : v01;
                    size_t xi = (size_t)rr * DD + cg0;
                    float2 xv = *(float2*)(ea.xbuf + xi);
                    float2 zv = *(float2*)(ea.zsbuf + xi);
                    float2 sv = *(float2*)(ea.srcp + xi);
                    float2 xo = {(1.0f - zv.x) * xv.x + zv.x * va + sv.x,
                                 (1.0f - zv.y) * xv.y + zv.y * vb + sv.y};
                    *(float2*)(ea.xbuf + xi) = xo;
                }
            }
        }
    }
}

// ---------------- fused causal flash attention (fp16 MMA) ----------------
#define FBM 128
#define FBN 64
#define FP 72   // pitch in halves
#define FLASH_SMEM ((FBM*FP + FBN*FP + FBN*FP + FBM*FP) * 2)

__global__ __launch_bounds__(256) void flash_attn_kernel(
        const __half* __restrict__ QKV, __half* __restrict__ O) {
    extern __shared__ char dynsm[];
    __half* Qs = (__half*)dynsm;
    __half* Ks = Qs + FBM * FP;
    __half* Vt = Ks + FBN * FP;
    __half* Ps = Vt + FBN * FP;

    const int tx = threadIdx.x;
    const int warp = tx >> 5;
    const int lane = tx & 31;
    const int g  = lane >> 2;
    const int tg = lane & 3;
    const int qb = gridDim.x - 1 - blockIdx.x;
    const int bh = blockIdx.y;
    const int bb = bh >> 4, hh = bh & 15;
    const int qbase = qb * FBM;

    const __half* qptr = QKV + (size_t)bb * TT * QKVLD + hh * HD;
    const __half* kptr = qptr + 1024;
    const __half* vptr = qptr + 2048;

    #pragma unroll
    for (int i = 0; i < 4; i++) {
        int idx = tx + i * 256;
        int r = idx >> 3, c8 = (idx & 7) * 8;
        *(uint4*)&Qs[r * FP + c8] =
            *(const uint4*)(qptr + (size_t)(qbase + r) * QKVLD + c8);
    }

    float m0 = -1e30f, m1 = -1e30f, l0 = 0.f, l1 = 0.f;
    float o[8][4];
    #pragma unroll
    for (int nt = 0; nt < 8; nt++)
        #pragma unroll
        for (int c = 0; c < 4; c++) o[nt][c] = 0.f;

    const int myrow0 = qbase + warp * 16;
    const float sl2e = 0.125f * 1.44269504088896f;

    const int kbmax = 2 * qb + 1;
    for (int kb = 0; kb <= kbmax; kb++) {
        __syncthreads();
        #pragma unroll
        for (int i = 0; i < 2; i++) {
            int idx = tx + i * 256;
            int r = idx >> 3, c8 = (idx & 7) * 8;
            *(uint4*)&Ks[r * FP + c8] =
                *(const uint4*)(kptr + (size_t)(kb * FBN + r) * QKVLD + c8);
        }
        #pragma unroll
        for (int i = 0; i < 2; i++) {
            int idx = tx + i * 256;
            int token = idx >> 3, d8 = (idx & 7) * 8;
            uint4 raw = *(const uint4*)(vptr + (size_t)(kb * FBN + token) * QKVLD + d8);
            const __half* hv = (const __half*)&raw;
            int tsw = token ^ (2 * (idx & 7));
            #pragma unroll
            for (int j = 0; j < 8; j++)
                Vt[(d8 + j) * FP + tsw] = hv[j];
        }
        __syncthreads();

        if (kb * FBN > myrow0 + 15) continue;

        float s[8][4];
        #pragma unroll
        for (int nt = 0; nt < 8; nt++)
            #pragma unroll
            for (int c = 0; c < 4; c++) s[nt][c] = 0.f;

        #pragma unroll
        for (int ks = 0; ks < 4; ks++) {
            const int kc = ks * 16;
            uint32_t a[4];
            const __half* p = &Qs[(warp * 16 + g) * FP + kc + 2 * tg];
            a[0] = *(const uint32_t*)p;
            a[1] = *(const uint32_t*)(p + 8 * FP);
            a[2] = *(const uint32_t*)(p + 8);
            a[3] = *(const uint32_t*)(p + 8 * FP + 8);
            #pragma unroll
            for (int nt = 0; nt < 8; nt++) {
                uint32_t b[2];
                const __half* q = &Ks[(nt * 8 + g) * FP + kc + 2 * tg];
                b[0] = *(const uint32_t*)q;
                b[1] = *(const uint32_t*)(q + 8);
                mma_f16(s[nt], a, b);
            }
        }

        const int r0 = myrow0 + g, r1 = r0 + 8;
        const bool dm = (kb >= 2 * qb);
        #pragma unroll
        for (int nt = 0; nt < 8; nt++) {
            int c0 = kb * FBN + nt * 8 + 2 * tg;
            s[nt][0] *= sl2e; s[nt][1] *= sl2e;
            s[nt][2] *= sl2e; s[nt][3] *= sl2e;
            if (dm) {
                if (c0     > r0) s[nt][0] = -1e30f;
                if (c0 + 1 > r0) s[nt][1] = -1e30f;
                if (c0     > r1) s[nt][2] = -1e30f;
                if (c0 + 1 > r1) s[nt][3] = -1e30f;
            }
        }

        float rm0 = -1e30f, rm1 = -1e30f;
        #pragma unroll
        for (int nt = 0; nt < 8; nt++) {
            rm0 = fmaxf(rm0, fmaxf(s[nt][0], s[nt][1]));
            rm1 = fmaxf(rm1, fmaxf(s[nt][2], s[nt][3]));
        }
        rm0 = fmaxf(rm0, __shfl_xor_sync(0xffffffffu, rm0, 1));
        rm0 = fmaxf(rm0, __shfl_xor_sync(0xffffffffu, rm0, 2));
        rm1 = fmaxf(rm1, __shfl_xor_sync(0xffffffffu, rm1, 1));
        rm1 = fmaxf(rm1, __shfl_xor_sync(0xffffffffu, rm1, 2));
        float mn0 = fmaxf(m0, rm0), mn1 = fmaxf(m1, rm1);
        float al0 = exp2a(m0 - mn0), al1 = exp2a(m1 - mn1);
        m0 = mn0; m1 = mn1;

        __syncwarp();
        float rs0 = 0.f, rs1 = 0.f;
        #pragma unroll
        for (int nt = 0; nt < 8; nt++) {
            float p0 = exp2a(s[nt][0] - m0);
            float p1 = exp2a(s[nt][1] - m0);
            float p2 = exp2a(s[nt][2] - m1);
            float p3 = exp2a(s[nt][3] - m1);
            rs0 += p0 + p1;
            rs1 += p2 + p3;
            __half* pp = &Ps[(warp * 16 + g) * FP + nt * 8 + 2 * tg];
            *(__half2*)pp = __floats2half2_rn(p0, p1);
            *(__half2*)(pp + 8 * FP) = __floats2half2_rn(p2, p3);
        }
        rs0 += __shfl_xor_sync(0xffffffffu, rs0, 1);
        rs0 += __shfl_xor_sync(0xffffffffu, rs0, 2);
        rs1 += __shfl_xor_sync(0xffffffffu, rs1, 1);
        rs1 += __shfl_xor_sync(0xffffffffu, rs1, 2);
        l0 = l0 * al0 + rs0;
        l1 = l1 * al1 + rs1;
        #pragma unroll
        for (int nt = 0; nt < 8; nt++) {
            o[nt][0] *= al0; o[nt][1] *= al0;
            o[nt][2] *= al1; o[nt][3] *= al1;
        }
        __syncwarp();

        #pragma unroll
        for (int ks = 0; ks < 4; ks++) {
            const int kc = ks * 16;
            uint32_t a[4];
            const __half* p = &Ps[(warp * 16 + g) * FP + kc + 2 * tg];
            a[0] = *(const uint32_t*)p;
            a[1] = *(const uint32_t*)(p + 8 * FP);
            a[2] = *(const uint32_t*)(p + 8);
            a[3] = *(const uint32_t*)(p + 8 * FP + 8);
            #pragma unroll
            for (int nt = 0; nt < 8; nt++) {
                uint32_t b[2];
                const int d = nt * 8 + g;
                const int sw = 2 * (nt & 7);
                b[0] = *(const uint32_t*)&Vt[d * FP + ((kc + 2 * tg) ^ sw)];
                b[1] = *(const uint32_t*)&Vt[d * FP + ((kc + 2 * tg + 8) ^ sw)];
                mma_f16(o[nt], a, b);
            }
        }
    }

    float i0 = 1.0f / l0, i1 = 1.0f / l1;
    __half* ob = O + ((size_t)bb * TT + myrow0 + g) * DD + hh * HD;
    #pragma unroll
    for (int nt = 0; nt < 8; nt++) {
        int c = nt * 8 + 2 * tg;
        *(__half2*)(ob + c) = __floats2half2_rn(o[nt][0] * i0, o[nt][1] * i0);
        *(__half2*)(ob + (size_t)8 * DD + c) = __floats2half2_rn(o[nt][2] * i1, o[nt][3] * i1);
    }
}

// ---------------- host orchestration ----------------
static void* symv(const void* s) {
    void* p = nullptr;
    cudaGetSymbolAddress(&p, s);
    return p;
}

extern "C" void kernel_launch(void* const* d_in, const int* in_sizes, int n_in,
                              void* d_out, int out_size) {
    const float* seq  = (const float*)d_in[0];
    const float* Wq   = (const float*)d_in[1];
    const float* bq   = (const float*)d_in[2];
    const float* Wk   = (const float*)d_in[3];
    const float* bk   = (const float*)d_in[4];
    const float* Wv   = (const float*)d_in[5];
    const float* bv   = (const float*)d_in[6];
    const float* Wo   = (const float*)d_in[7];
    const float* bo   = (const float*)d_in[8];
    const float* Wz   = (const float*)d_in[9];
    const float* bz   = (const float*)d_in[10];
    const float* Wr   = (const float*)d_in[11];
    const float* br   = (const float*)d_in[12];
    const float* W1   = (const float*)d_in[13];
    const float* b1   = (const float*)d_in[14];
    const float* W2   = (const float*)d_in[15];
    const float* b2   = (const float*)d_in[16];
    const float* ln1w = (const float*)d_in[17];
    const float* ln1b = (const float*)d_in[18];
    const float* ln2w = (const float*)d_in[19];
    const float* ln2b = (const float*)d_in[20];
    const float* lnfw = (const float*)d_in[21];
    const float* lnfb = (const float*)d_in[22];

    float*  x     = (float*)symv(g_x);
    __half* xn    = (__half*)symv(g_xn);
    __half* qkvzr = (__half*)symv(g_qkvzr);
    __half* y     = (__half*)symv(g_y);
    float*  zs    = (float*)symv(g_zs);
    __half* h1    = (__half*)symv(g_h1);
    __half* wtqkv = (__half*)symv(g_wtqkvzr);
    __half* wto   = (__half*)symv(g_wto);
    __half* wt1   = (__half*)symv(g_wt1);
    __half* wt2   = (__half*)symv(g_wt2);
    float*  bcat  = (float*)symv(g_bcat);

    static bool attr_done = false;
    if (!attr_done) {
        cudaFuncSetAttribute(flash_attn_kernel,
                             cudaFuncAttributeMaxDynamicSharedMemorySize, FLASH_SMEM);
        cudaFuncSetAttribute(gemm_f16_kernel,
                             cudaFuncAttributeMaxDynamicSharedMemorySize, GEMM_SMEM);
        attr_done = true;
    }

    const int nElem = NTOK * DD;
    const int eblocks = (nElem + 255) / 256;

    // ---- batched weight pre-transpose (8 launches) + bias packing ----
    {
        size_t dsz = (size_t)DD * DD;
        dim3 tD(DD / 32, DD / 32, NL);
        dim3 t1(DF / 32, DD / 32, NL);
        dim3 t2(DD / 32, DF / 32, NL);
        transpose_h_kernel<<<tD, 256>>>(Wq, wtqkv + 0ull * dsz, DD, DD, dsz, (size_t)QKVLD * DD);
        transpose_h_kernel<<<tD, 256>>>(Wk, wtqkv + 1ull * dsz, DD, DD, dsz, (size_t)QKVLD * DD);
        transpose_h_kernel<<<tD, 256>>>(Wv, wtqkv + 2ull * dsz, DD, DD, dsz, (size_t)QKVLD * DD);
        transpose_h_kernel<<<tD, 256>>>(Wz, wtqkv + 3ull * dsz, DD, DD, dsz, (size_t)QKVLD * DD);
        transpose_h_kernel<<<tD, 256>>>(Wr, wtqkv + 4ull * dsz, DD, DD, dsz, (size_t)QKVLD * DD);
        transpose_h_kernel<<<tD, 256>>>(Wo, wto, DD, DD, dsz, dsz);
        transpose_h_kernel<<<t1, 256>>>(W1, wt1, DD, DF, (size_t)DD * DF, (size_t)DF * DD);
        transpose_h_kernel<<<t2, 256>>>(W2, wt2, DF, DD, (size_t)DF * DD, (size_t)DD * DF);
    }
    biaspack_kernel<<<(NL * QKVLD + 255) / 256, 256>>>(bq, bk, bv, bz, br, bcat);

    copy_kernel<<<eblocks, 256>>>(x, seq, nElem);

    dim3 gQKVZR(QKVLD / GBN, NTOK / GBM);  // (40, 32)
    dim3 gO(DD / GBN, NTOK / GBM);         // (8, 32)
    dim3 gM1(DF / GBN, NTOK / GBM);        // (32, 32)
    dim3 gFA(TT / FBM, BB * HH);           // (16, 32)

    EpiArgs eaNone = {nullptr, nullptr, nullptr, nullptr};

    for (int l = 0; l < NL; l++) {
        layernorm_kernel<__half><<<NTOK, 256>>>(x, ln1w + l * DD, ln1b + l * DD, xn);

        gemm_f16_kernel<<<gQKVZR, 256, GEMM_SMEM>>>(
            xn, wtqkv + (size_t)l * QKVLD * DD, bcat + l * QKVLD, qkvzr,
            DD, QKVLD, 0, 1, eaNone);

        flash_attn_kernel<<<gFA, 256, FLASH_SMEM>>>(qkvzr, y);

        // Wo GEMM + fused gate1
        EpiArgs ea1 = {x, zs, qkvzr, nullptr};
        gemm_f16_kernel<<<gO, 256, GEMM_SMEM>>>(
            y, wto + (size_t)l * DD * DD, bo + l * DD, nullptr,
            DD, DD, 2, 0, ea1);

        layernorm_kernel<__half><<<NTOK, 256>>>(x, ln2w + l * DD, ln2b + l * DD, xn);
        gemm_f16_kernel<<<gM1, 256, GEMM_SMEM>>>(
            xn, wt1 + (size_t)l * DF * DD, b1 + l * DF, h1,
            DD, DF, 1, 1, eaNone);

        // W2 GEMM + fused gate2
        EpiArgs ea2 = {x, zs, nullptr, seq};
        gemm_f16_kernel<<<gO, 256, GEMM_SMEM>>>(
            h1, wt2 + (size_t)l * DD * DF, b2 + l * DD, nullptr,
            DF, DD, 3, 0, ea2);
    }

    layernorm_kernel<float><<<NTOK, 256>>>(x, lnfw, lnfb, (float*)d_out);
}

// round 7
// speedup vs baseline: 1.2111x; 1.2111x over previous
#include <cuda_runtime.h>
#include <cuda_fp16.h>
#include <math.h>
#include <stdint.h>

// ---------------- problem constants ----------------
#define BB 2
#define TT 2048
#define DD 1024
#define HH 16
#define HD 64
#define NL 6
#define DF 4096
#define NTOK (BB*TT)          // 4096 rows
#define QKVLD 5120            // fused QKVZR row stride
#define EPSLN 1e-5f

// ---------------- device scratch (no allocs allowed) ----------------
__device__ float  g_x   [NTOK*DD];
__device__ __half g_xn  [NTOK*DD];
__device__ __half g_qkvzr[(size_t)NTOK*QKVLD];
__device__ __half g_y   [NTOK*DD];
__device__ float  g_zs  [NTOK*DD];
__device__ __half g_h1  [(size_t)NTOK*DF];

// transposed fp16 weights, K-major [N][K]
__device__ __half g_wtqkvzr[(size_t)NL*QKVLD*DD];
__device__ __half g_wto    [(size_t)NL*DD*DD];
__device__ __half g_wt1    [(size_t)NL*DF*DD];
__device__ __half g_wt2    [(size_t)NL*DD*DF];
__device__ float  g_bcat   [NL*QKVLD];

// ---------------- helpers ----------------
__device__ __forceinline__ float exp2a(float x) {
    float y;
    asm("ex2.approx.f32 %0, %1;" : "=f"(y) : "f"(x));
    return y;
}

__device__ __forceinline__ void mma_f16(float* d, const uint32_t* a, const uint32_t* b) {
    asm volatile(
        "mma.sync.aligned.m16n8k16.row.col.f32.f16.f16.f32 "
        "{%0,%1,%2,%3}, {%4,%5,%6,%7}, {%8,%9}, {%0,%1,%2,%3};"
        : "+f"(d[0]), "+f"(d[1]), "+f"(d[2]), "+f"(d[3])
        : "r"(a[0]), "r"(a[1]), "r"(a[2]), "r"(a[3]),
          "r"(b[0]), "r"(b[1]));
}

__device__ __forceinline__ float sigmoidf_(float x) { return 1.0f / (1.0f + expf(-x)); }

__device__ __forceinline__ uint32_t smem_u32(const void* p) {
    uint32_t a;
    asm("{ .reg .u64 t; cvta.to.shared.u64 t, %1; cvt.u32.u64 %0, t; }" : "=r"(a) : "l"(p));
    return a;
}

__device__ __forceinline__ void cp16(uint32_t dst, const void* src) {
    asm volatile("cp.async.cg.shared.global [%0], [%1], 16;" :: "r"(dst), "l"(src) : "memory");
}
#define CP_COMMIT() asm volatile("cp.async.commit_group;" ::: "memory")
#define CP_WAIT(n)  asm volatile("cp.async.wait_group %0;" :: "n"(n) : "memory")

// ---------------- small elementwise kernels ----------------
__global__ void copy_kernel(float* __restrict__ dst, const float* __restrict__ src, int n) {
    int i = blockIdx.x * blockDim.x + threadIdx.x;
    if (i < n) dst[i] = src[i];
}

// ---------------- layernorm (fp16 out / fp32 out) ----------------
template <typename OutT>
__global__ __launch_bounds__(256) void layernorm_kernel(
        const float* __restrict__ x, const float* __restrict__ w,
        const float* __restrict__ b, OutT* __restrict__ out) {
    int row = blockIdx.x;
    const float* xr = x + (size_t)row * DD;
    OutT* orow = out + (size_t)row * DD;
    int tid = threadIdx.x;
    __shared__ float s1[256], s2[256];
    float sum = 0.f, ss = 0.f;
    #pragma unroll
    for (int j = tid; j < DD; j += 256) { float v = xr[j]; sum += v; ss += v * v; }
    s1[tid] = sum; s2[tid] = ss;
    __syncthreads();
    for (int s = 128; s > 0; s >>= 1) {
        if (tid < s) { s1[tid] += s1[tid + s]; s2[tid] += s2[tid + s]; }
        __syncthreads();
    }
    float mu = s1[0] * (1.0f / DD);
    float var = s2[0] * (1.0f / DD) - mu * mu;
    float rs = rsqrtf(var + EPSLN);
    for (int j = tid; j < DD; j += 256)
        orow[j] = (OutT)((xr[j] - mu) * rs * w[j] + b[j]);
}

// ---------------- batched weight transpose to fp16 (z = layer) ----------------
__global__ __launch_bounds__(256) void transpose_h_kernel(
        const float* __restrict__ src, __half* __restrict__ dst, int K, int N,
        size_t srcLS, size_t dstLS) {
    __shared__ float tile[32][33];
    const float* s = src + blockIdx.z * srcLS;
    __half* d = dst + blockIdx.z * dstLS;
    int k0 = blockIdx.y * 32, n0 = blockIdx.x * 32;
    int tx = threadIdx.x & 31, ty = threadIdx.x >> 5;
    #pragma unroll
    for (int i = 0; i < 4; i++)
        tile[ty + i * 8][tx] = s[(size_t)(k0 + ty + i * 8) * N + n0 + tx];
    __syncthreads();
    #pragma unroll
    for (int i = 0; i < 4; i++)
        d[(size_t)(n0 + ty + i * 8) * K + k0 + tx] = __float2half(tile[tx][ty + i * 8]);
}

__global__ void biaspack_kernel(const float* __restrict__ bq, const float* __restrict__ bk,
                                const float* __restrict__ bv, const float* __restrict__ bz,
                                const float* __restrict__ br, float* __restrict__ out) {
    int i = blockIdx.x * blockDim.x + threadIdx.x;
    if (i >= NL * QKVLD) return;
    int l = i / QKVLD, j = i % QKVLD;
    int m = j >> 10, c = j & 1023;
    const float* src = (m == 0) ? bq : (m == 1) ? bk : (m == 2) ? bv : (m == 3) ? bz : br;
    out[i] = src[l * 1024 + c];
}

// ---------------- fp16 tensor-core GEMM, 2-stage cp.async (R5-proven mainloop) ----------------
// C[M,N] = A[M,K](fp16) @ WT[N,K]^T(fp16) + bias. BM=BN=128, BK=64.
// epi: 0=bias->out, 1=bias+GELU->out, 2=gate1(x,zs), 3=gate2(x)
#define GBM 128
#define GBN 128
#define GBK 64
#define GP 72   // smem pitch in halves
#define GTILE (GBM*GP)
#define GEMM_SMEM (4*GTILE*2)   // A[2] + B[2] stages, halves -> 73.7KB (2 CTAs/SM)

struct EpiArgs {
    float* xbuf;            // gate modes: residual x (fp32, ld=DD)
    float* zsbuf;           // gate1: z out; gate2: z in
    const __half* qz;       // gate1: fused qkvzr (z/r logits)
    const float* srcp;      // gate2: original sequences
};

__global__ __launch_bounds__(256) void gemm_f16_kernel(
        const __half* __restrict__ A, const __half* __restrict__ WT,
        const float* __restrict__ bias, void* __restrict__ Cout,
        int K, int ldC, int epi, int outHalf, EpiArgs ea) {
    extern __shared__ char dynsm[];
    __half* As = (__half*)dynsm;
    __half* Bs = As + 2 * GTILE;

    const int tid  = threadIdx.x;
    const int warp = tid >> 5;
    const int lane = tid & 31;
    const int g    = lane >> 2;
    const int tg   = lane & 3;
    const int row0 = blockIdx.y * GBM;
    const int col0 = blockIdx.x * GBN;
    const int wm   = (warp >> 2) * 64;
    const int wn   = (warp & 3) * 32;

    const int fr = tid >> 3;
    const int fc = (tid & 7) * 8;

    float acc[4][4][4];
    #pragma unroll
    for (int i = 0; i < 4; i++)
        #pragma unroll
        for (int j = 0; j < 4; j++)
            #pragma unroll
            for (int c = 0; c < 4; c++) acc[i][j][c] = 0.f;

    const __half* Ag = A  + (size_t)row0 * K;
    const __half* Bg = WT + (size_t)col0 * K;
    const uint32_t as_base = smem_u32(As);
    const uint32_t bs_base = smem_u32(Bs);

    auto issue = [&](int it, int buf) {
        const int k0 = it * GBK;
        uint32_t ad = as_base + (buf * GTILE) * 2;
        uint32_t bd = bs_base + (buf * GTILE) * 2;
        #pragma unroll
        for (int i = 0; i < 4; i++) {
            int r = fr + i * 32;
            cp16(ad + (r * GP + fc) * 2, Ag + (size_t)r * K + k0 + fc);
            cp16(bd + (r * GP + fc) * 2, Bg + (size_t)r * K + k0 + fc);
        }
    };

    issue(0, 0);
    CP_COMMIT();

    const int nit = K / GBK;
    for (int it = 0; it < nit; it++) {
        const int buf = it & 1;
        if (it + 1 < nit) { issue(it + 1, buf ^ 1); CP_COMMIT(); CP_WAIT(1); }
        else              { CP_WAIT(0); }
        __syncthreads();

        const __half* Ab = As + buf * GTILE;
        const __half* Bb = Bs + buf * GTILE;
        #pragma unroll
        for (int ks = 0; ks < 4; ks++) {
            const int kc = ks * 16;
            uint32_t af[4][4], bf[4][2];
            #pragma unroll
            for (int fm = 0; fm < 4; fm++) {
                const __half* p = Ab + (wm + fm * 16 + g) * GP + kc + 2 * tg;
                af[fm][0] = *(const uint32_t*)p;
                af[fm][1] = *(const uint32_t*)(p + 8 * GP);
                af[fm][2] = *(const uint32_t*)(p + 8);
                af[fm][3] = *(const uint32_t*)(p + 8 * GP + 8);
            }
            #pragma unroll
            for (int fn = 0; fn < 4; fn++) {
                const __half* q = Bb + (wn + fn * 8 + g) * GP + kc + 2 * tg;
                bf[fn][0] = *(const uint32_t*)q;
                bf[fn][1] = *(const uint32_t*)(q + 8);
            }
            #pragma unroll
            for (int fm = 0; fm < 4; fm++)
                #pragma unroll
                for (int fn = 0; fn < 4; fn++)
                    mma_f16(acc[fm][fn], af[fm], bf[fn]);
        }
        __syncthreads();
    }

    // ---------------- epilogue ----------------
    #pragma unroll
    for (int fm = 0; fm < 4; fm++) {
        int r1 = row0 + wm + fm * 16 + g;
        #pragma unroll
        for (int fn = 0; fn < 4; fn++) {
            int cl = wn + fn * 8 + tg * 2;
            int cg0 = col0 + cl;
            float bz0 = bias[cg0];
            float bz1 = bias[cg0 + 1];
            float v00 = acc[fm][fn][0] + bz0;
            float v01 = acc[fm][fn][1] + bz1;
            float v10 = acc[fm][fn][2] + bz0;
            float v11 = acc[fm][fn][3] + bz1;

            if (epi == 0) {
                if (outHalf) {
                    __half* ch = (__half*)Cout;
                    *(__half2*)(ch + (size_t)r1 * ldC + cg0) = __floats2half2_rn(v00, v01);
                    *(__half2*)(ch + (size_t)(r1 + 8) * ldC + cg0) = __floats2half2_rn(v10, v11);
                } else {
                    float* cf = (float*)Cout;
                    float2 o0 = {v00, v01};
                    float2 o1 = {v10, v11};
                    *(float2*)(cf + (size_t)r1 * ldC + cg0) = o0;
                    *(float2*)(cf + (size_t)(r1 + 8) * ldC + cg0) = o1;
                }
            } else if (epi == 1) {
                v00 = 0.5f * v00 * (1.0f + erff(v00 * 0.70710678118654752440f));
                v01 = 0.5f * v01 * (1.0f + erff(v01 * 0.70710678118654752440f));
                v10 = 0.5f * v10 * (1.0f + erff(v10 * 0.70710678118654752440f));
                v11 = 0.5f * v11 * (1.0f + erff(v11 * 0.70710678118654752440f));
                __half* ch = (__half*)Cout;
                *(__half2*)(ch + (size_t)r1 * ldC + cg0) = __floats2half2_rn(v00, v01);
                *(__half2*)(ch + (size_t)(r1 + 8) * ldC + cg0) = __floats2half2_rn(v10, v11);
            } else if (epi == 2) {
                // gate1: x = (1-z)x + z*tanh(r*v); zs = z
                #pragma unroll
                for (int h = 0; h < 2; h++) {
                    int rr = r1 + h * 8;
                    float va = h ? v10 : v00;
                    float vb = h ? v11 : v01;
                    size_t qb_ = (size_t)rr * QKVLD + cg0;
                    __half2 zl = *(const __half2*)(ea.qz + qb_ + 3072);
                    __half2 rl = *(const __half2*)(ea.qz + qb_ + 4096);
                    float2 zf = __half22float2(zl);
                    float2 rf = __half22float2(rl);
                    float z0 = sigmoidf_(zf.x);
                    float z1 = sigmoidf_(zf.y);
                    float rg0 = sigmoidf_(rf.x);
                    float rg1 = sigmoidf_(rf.y);
                    size_t xi = (size_t)rr * DD + cg0;
                    float2 xv = *(float2*)(ea.xbuf + xi);
                    float h0 = tanhf(rg0 * va);
                    float h1v = tanhf(rg1 * vb);
                    float2 xo = {(1.0f - z0) * xv.x + z0 * h0,
                                 (1.0f - z1) * xv.y + z1 * h1v};
                    *(float2*)(ea.xbuf + xi) = xo;
                    float2 zo = {z0, z1};
                    *(float2*)(ea.zsbuf + xi) = zo;
                }
            } else {
                // gate2: x = (1-z)x + z*v + src
                #pragma unroll
                for (int h = 0; h < 2; h++) {
                    int rr = r1 + h * 8;
                    float va = h ? v10 : v00;
                    float vb = h ? v11 : v01;
                    size_t xi = (size_t)rr * DD + cg0;
                    float2 xv = *(float2*)(ea.xbuf + xi);
                    float2 zv = *(float2*)(ea.zsbuf + xi);
                    float2 sv = *(float2*)(ea.srcp + xi);
                    float2 xo = {(1.0f - zv.x) * xv.x + zv.x * va + sv.x,
                                 (1.0f - zv.y) * xv.y + zv.y * vb + sv.y};
                    *(float2*)(ea.xbuf + xi) = xo;
                }
            }
        }
    }
}

// ---------------- fused causal flash attention (fp16 MMA) ----------------
#define FBM 128
#define FBN 64
#define FP 72   // pitch in halves
#define FLASH_SMEM ((FBM*FP + FBN*FP + FBN*FP + FBM*FP) * 2)

__global__ __launch_bounds__(256) void flash_attn_kernel(
        const __half* __restrict__ QKV, __half* __restrict__ O) {
    extern __shared__ char dynsm[];
    __half* Qs = (__half*)dynsm;
    __half* Ks = Qs + FBM * FP;
    __half* Vt = Ks + FBN * FP;
    __half* Ps = Vt + FBN * FP;

    const int tx = threadIdx.x;
    const int warp = tx >> 5;
    const int lane = tx & 31;
    const int g  = lane >> 2;
    const int tg = lane & 3;
    const int qb = gridDim.x - 1 - blockIdx.x;
    const int bh = blockIdx.y;
    const int bb = bh >> 4, hh = bh & 15;
    const int qbase = qb * FBM;

    const __half* qptr = QKV + (size_t)bb * TT * QKVLD + hh * HD;
    const __half* kptr = qptr + 1024;
    const __half* vptr = qptr + 2048;

    #pragma unroll
    for (int i = 0; i < 4; i++) {
        int idx = tx + i * 256;
        int r = idx >> 3, c8 = (idx & 7) * 8;
        *(uint4*)&Qs[r * FP + c8] =
            *(const uint4*)(qptr + (size_t)(qbase + r) * QKVLD + c8);
    }

    float m0 = -1e30f, m1 = -1e30f, l0 = 0.f, l1 = 0.f;
    float o[8][4];
    #pragma unroll
    for (int nt = 0; nt < 8; nt++)
        #pragma unroll
        for (int c = 0; c < 4; c++) o[nt][c] = 0.f;

    const int myrow0 = qbase + warp * 16;
    const float sl2e = 0.125f * 1.44269504088896f;

    const int kbmax = 2 * qb + 1;
    for (int kb = 0; kb <= kbmax; kb++) {
        __syncthreads();
        #pragma unroll
        for (int i = 0; i < 2; i++) {
            int idx = tx + i * 256;
            int r = idx >> 3, c8 = (idx & 7) * 8;
            *(uint4*)&Ks[r * FP + c8] =
                *(const uint4*)(kptr + (size_t)(kb * FBN + r) * QKVLD + c8);
        }
        #pragma unroll
        for (int i = 0; i < 2; i++) {
            int idx = tx + i * 256;
            int token = idx >> 3, d8 = (idx & 7) * 8;
            uint4 raw = *(const uint4*)(vptr + (size_t)(kb * FBN + token) * QKVLD + d8);
            const __half* hv = (const __half*)&raw;
            int tsw = token ^ (2 * (idx & 7));
            #pragma unroll
            for (int j = 0; j < 8; j++)
                Vt[(d8 + j) * FP + tsw] = hv[j];
        }
        __syncthreads();

        if (kb * FBN > myrow0 + 15) continue;

        float s[8][4];
        #pragma unroll
        for (int nt = 0; nt < 8; nt++)
            #pragma unroll
            for (int c = 0; c < 4; c++) s[nt][c] = 0.f;

        #pragma unroll
        for (int ks = 0; ks < 4; ks++) {
            const int kc = ks * 16;
            uint32_t a[4];
            const __half* p = &Qs[(warp * 16 + g) * FP + kc + 2 * tg];
            a[0] = *(const uint32_t*)p;
            a[1] = *(const uint32_t*)(p + 8 * FP);
            a[2] = *(const uint32_t*)(p + 8);
            a[3] = *(const uint32_t*)(p + 8 * FP + 8);
            #pragma unroll
            for (int nt = 0; nt < 8; nt++) {
                uint32_t b[2];
                const __half* q = &Ks[(nt * 8 + g) * FP + kc + 2 * tg];
                b[0] = *(const uint32_t*)q;
                b[1] = *(const uint32_t*)(q + 8);
                mma_f16(s[nt], a, b);
            }
        }

        const int r0 = myrow0 + g, r1 = r0 + 8;
        const bool dm = (kb >= 2 * qb);
        #pragma unroll
        for (int nt = 0; nt < 8; nt++) {
            int c0 = kb * FBN + nt * 8 + 2 * tg;
            s[nt][0] *= sl2e; s[nt][1] *= sl2e;
            s[nt][2] *= sl2e; s[nt][3] *= sl2e;
            if (dm) {
                if (c0     > r0) s[nt][0] = -1e30f;
                if (c0 + 1 > r0) s[nt][1] = -1e30f;
                if (c0     > r1) s[nt][2] = -1e30f;
                if (c0 + 1 > r1) s[nt][3] = -1e30f;
            }
        }

        float rm0 = -1e30f, rm1 = -1e30f;
        #pragma unroll
        for (int nt = 0; nt < 8; nt++) {
            rm0 = fmaxf(rm0, fmaxf(s[nt][0], s[nt][1]));
            rm1 = fmaxf(rm1, fmaxf(s[nt][2], s[nt][3]));
        }
        rm0 = fmaxf(rm0, __shfl_xor_sync(0xffffffffu, rm0, 1));
        rm0 = fmaxf(rm0, __shfl_xor_sync(0xffffffffu, rm0, 2));
        rm1 = fmaxf(rm1, __shfl_xor_sync(0xffffffffu, rm1, 1));
        rm1 = fmaxf(rm1, __shfl_xor_sync(0xffffffffu, rm1, 2));
        float mn0 = fmaxf(m0, rm0), mn1 = fmaxf(m1, rm1);
        float al0 = exp2a(m0 - mn0), al1 = exp2a(m1 - mn1);
        m0 = mn0; m1 = mn1;

        __syncwarp();
        float rs0 = 0.f, rs1 = 0.f;
        #pragma unroll
        for (int nt = 0; nt < 8; nt++) {
            float p0 = exp2a(s[nt][0] - m0);
            float p1 = exp2a(s[nt][1] - m0);
            float p2 = exp2a(s[nt][2] - m1);
            float p3 = exp2a(s[nt][3] - m1);
            rs0 += p0 + p1;
            rs1 += p2 + p3;
            __half* pp = &Ps[(warp * 16 + g) * FP + nt * 8 + 2 * tg];
            *(__half2*)pp = __floats2half2_rn(p0, p1);
            *(__half2*)(pp + 8 * FP) = __floats2half2_rn(p2, p3);
        }
        rs0 += __shfl_xor_sync(0xffffffffu, rs0, 1);
        rs0 += __shfl_xor_sync(0xffffffffu, rs0, 2);
        rs1 += __shfl_xor_sync(0xffffffffu, rs1, 1);
        rs1 += __shfl_xor_sync(0xffffffffu, rs1, 2);
        l0 = l0 * al0 + rs0;
        l1 = l1 * al1 + rs1;
        #pragma unroll
        for (int nt = 0; nt < 8; nt++) {
            o[nt][0] *= al0; o[nt][1] *= al0;
            o[nt][2] *= al1; o[nt][3] *= al1;
        }
        __syncwarp();

        #pragma unroll
        for (int ks = 0; ks < 4; ks++) {
            const int kc = ks * 16;
            uint32_t a[4];
            const __half* p = &Ps[(warp * 16 + g) * FP + kc + 2 * tg];
            a[0] = *(const uint32_t*)p;
            a[1] = *(const uint32_t*)(p + 8 * FP);
            a[2] = *(const uint32_t*)(p + 8);
            a[3] = *(const uint32_t*)(p + 8 * FP + 8);
            #pragma unroll
            for (int nt = 0; nt < 8; nt++) {
                uint32_t b[2];
                const int d = nt * 8 + g;
                const int sw = 2 * (nt & 7);
                b[0] = *(const uint32_t*)&Vt[d * FP + ((kc + 2 * tg) ^ sw)];
                b[1] = *(const uint32_t*)&Vt[d * FP + ((kc + 2 * tg + 8) ^ sw)];
                mma_f16(o[nt], a, b);
            }
        }
    }

    float i0 = 1.0f / l0, i1 = 1.0f / l1;
    __half* ob = O + ((size_t)bb * TT + myrow0 + g) * DD + hh * HD;
    #pragma unroll
    for (int nt = 0; nt < 8; nt++) {
        int c = nt * 8 + 2 * tg;
        *(__half2*)(ob + c) = __floats2half2_rn(o[nt][0] * i0, o[nt][1] * i0);
        *(__half2*)(ob + (size_t)8 * DD + c) = __floats2half2_rn(o[nt][2] * i1, o[nt][3] * i1);
    }
}

// ---------------- host orchestration ----------------
static void* symv(const void* s) {
    void* p = nullptr;
    cudaGetSymbolAddress(&p, s);
    return p;
}

extern "C" void kernel_launch(void* const* d_in, const int* in_sizes, int n_in,
                              void* d_out, int out_size) {
    const float* seq  = (const float*)d_in[0];
    const float* Wq   = (const float*)d_in[1];
    const float* bq   = (const float*)d_in[2];
    const float* Wk   = (const float*)d_in[3];
    const float* bk   = (const float*)d_in[4];
    const float* Wv   = (const float*)d_in[5];
    const float* bv   = (const float*)d_in[6];
    const float* Wo   = (const float*)d_in[7];
    const float* bo   = (const float*)d_in[8];
    const float* Wz   = (const float*)d_in[9];
    const float* bz   = (const float*)d_in[10];
    const float* Wr   = (const float*)d_in[11];
    const float* br   = (const float*)d_in[12];
    const float* W1   = (const float*)d_in[13];
    const float* b1   = (const float*)d_in[14];
    const float* W2   = (const float*)d_in[15];
    const float* b2   = (const float*)d_in[16];
    const float* ln1w = (const float*)d_in[17];
    const float* ln1b = (const float*)d_in[18];
    const float* ln2w = (const float*)d_in[19];
    const float* ln2b = (const float*)d_in[20];
    const float* lnfw = (const float*)d_in[21];
    const float* lnfb = (const float*)d_in[22];

    float*  x     = (float*)symv(g_x);
    __half* xn    = (__half*)symv(g_xn);
    __half* qkvzr = (__half*)symv(g_qkvzr);
    __half* y     = (__half*)symv(g_y);
    float*  zs    = (float*)symv(g_zs);
    __half* h1    = (__half*)symv(g_h1);
    __half* wtqkv = (__half*)symv(g_wtqkvzr);
    __half* wto   = (__half*)symv(g_wto);
    __half* wt1   = (__half*)symv(g_wt1);
    __half* wt2   = (__half*)symv(g_wt2);
    float*  bcat  = (float*)symv(g_bcat);

    static bool attr_done = false;
    if (!attr_done) {
        cudaFuncSetAttribute(flash_attn_kernel,
                             cudaFuncAttributeMaxDynamicSharedMemorySize, FLASH_SMEM);
        cudaFuncSetAttribute(gemm_f16_kernel,
                             cudaFuncAttributeMaxDynamicSharedMemorySize, GEMM_SMEM);
        attr_done = true;
    }

    const int nElem = NTOK * DD;
    const int eblocks = (nElem + 255) / 256;

    // ---- batched weight pre-transpose (8 launches) + bias packing ----
    {
        size_t dsz = (size_t)DD * DD;
        dim3 tD(DD / 32, DD / 32, NL);
        dim3 t1(DF / 32, DD / 32, NL);
        dim3 t2(DD / 32, DF / 32, NL);
        transpose_h_kernel<<<tD, 256>>>(Wq, wtqkv + 0ull * dsz, DD, DD, dsz, (size_t)QKVLD * DD);
        transpose_h_kernel<<<tD, 256>>>(Wk, wtqkv + 1ull * dsz, DD, DD, dsz, (size_t)QKVLD * DD);
        transpose_h_kernel<<<tD, 256>>>(Wv, wtqkv + 2ull * dsz, DD, DD, dsz, (size_t)QKVLD * DD);
        transpose_h_kernel<<<tD, 256>>>(Wz, wtqkv + 3ull * dsz, DD, DD, dsz, (size_t)QKVLD * DD);
        transpose_h_kernel<<<tD, 256>>>(Wr, wtqkv + 4ull * dsz, DD, DD, dsz, (size_t)QKVLD * DD);
        transpose_h_kernel<<<tD, 256>>>(Wo, wto, DD, DD, dsz, dsz);
        transpose_h_kernel<<<t1, 256>>>(W1, wt1, DD, DF, (size_t)DD * DF, (size_t)DF * DD);
        transpose_h_kernel<<<t2, 256>>>(W2, wt2, DF, DD, (size_t)DF * DD, (size_t)DD * DF);
    }
    biaspack_kernel<<<(NL * QKVLD + 255) / 256, 256>>>(bq, bk, bv, bz, br, bcat);

    copy_kernel<<<eblocks, 256>>>(x, seq, nElem);

    dim3 gQKVZR(QKVLD / GBN, NTOK / GBM);  // (40, 32)
    dim3 gO(DD / GBN, NTOK / GBM);         // (8, 32)
    dim3 gM1(DF / GBN, NTOK / GBM);        // (32, 32)
    dim3 gFA(TT / FBM, BB * HH);           // (16, 32)

    EpiArgs eaNone = {nullptr, nullptr, nullptr, nullptr};

    for (int l = 0; l < NL; l++) {
        layernorm_kernel<__half><<<NTOK, 256>>>(x, ln1w + l * DD, ln1b + l * DD, xn);

        gemm_f16_kernel<<<gQKVZR, 256, GEMM_SMEM>>>(
            xn, wtqkv + (size_t)l * QKVLD * DD, bcat + l * QKVLD, qkvzr,
            DD, QKVLD, 0, 1, eaNone);

        flash_attn_kernel<<<gFA, 256, FLASH_SMEM>>>(qkvzr, y);

        // Wo GEMM + fused gate1
        EpiArgs ea1 = {x, zs, qkvzr, nullptr};
        gemm_f16_kernel<<<gO, 256, GEMM_SMEM>>>(
            y, wto + (size_t)l * DD * DD, bo + l * DD, nullptr,
            DD, DD, 2, 0, ea1);

        layernorm_kernel<__half><<<NTOK, 256>>>(x, ln2w + l * DD, ln2b + l * DD, xn);
        gemm_f16_kernel<<<gM1, 256, GEMM_SMEM>>>(
            xn, wt1 + (size_t)l * DF * DD, b1 + l * DF, h1,
            DD, DF, 1, 1, eaNone);

        // W2 GEMM + fused gate2
        EpiArgs ea2 = {x, zs, nullptr, seq};
        gemm_f16_kernel<<<gO, 256, GEMM_SMEM>>>(
            h1, wt2 + (size_t)l * DD * DF, b2 + l * DD, nullptr,
            DF, DD, 3, 0, ea2);
    }

    layernorm_kernel<float><<<NTOK, 256>>>(x, lnfw, lnfb, (float*)d_out);
}